// round 2
// baseline (speedup 1.0000x reference)
#include <cuda_runtime.h>
#include <cstdint>

#define S_DIM 512
#define O_DIM 4096
#define I_DIM 4096

// ---------------- scratch (device globals; no allocations allowed) -------
__device__ float g_P1[O_DIM];
__device__ float g_N1[O_DIM];
__device__ float g_P2[O_DIM];
__device__ float g_PB[O_DIM];
__device__ float g_NB[O_DIM];
__device__ float g_nrb[O_DIM];   // -relu(bias)
__device__ float g_bias[O_DIM];
__device__ float g_C1[(size_t)S_DIM * O_DIM];
__device__ float g_C2[(size_t)S_DIM * O_DIM];
__device__ float g_D[S_DIM];
__device__ int   g_anyC2;

// ---------------- kernel 0: zero the C2 flag ------------------------------
__global__ void kern_zero() { g_anyC2 = 0; }

// ---------------- kernel 1: per-output-neuron scalars ---------------------
__global__ void kern_prep(const float* __restrict__ bias,
                          const float* __restrict__ lbp,
                          const float* __restrict__ ubp,
                          const float* __restrict__ alpha) {
    int o = blockIdx.x * blockDim.x + threadIdx.x;
    if (o >= O_DIM) return;
    float b  = bias[o];
    float lb = lbp[o];
    float ub = ubp[o];
    float a  = alpha[o];
    float one_a = 1.0f - a;

    // CROWN relaxation scalars (always applied, matching reference)
    float lb_r = fminf(lb, 0.0f);
    float ub_r = fmaxf(ub, 0.0f);
    ub_r = fmaxf(ub_r, lb_r + 1e-8f);
    float ud  = ub_r / (ub_r - lb_r);
    float upb = -lb_r * ud;
    float ld  = (ud > 0.5f) ? 1.0f : 0.0f;
    float lower_d = (fabsf(lb) >= fabsf(ub)) ? 1.0f : 0.0f;

    float P1, N1, P2, PB, NB;
    if (ub <= 0.0f) {                   // stable-negative: simplex coeffs = 0
        P1 = a * ud;
        N1 = a * ld;
        P2 = 0.0f;
        PB = upb + ud * a * b;
        NB = ld * a * b;
    } else if (lb >= 0.0f) {            // stable-positive: coeffs = weight
        P1 = a * ud + one_a;
        N1 = a * ld + one_a;
        P2 = 0.0f;
        PB = one_a * b + upb + ud * a * b;
        NB = one_a * b + ld * a * b;
    } else {                            // unstable
        P1 = a * ud;
        N1 = a * ld + one_a * lower_d;
        P2 = one_a;                     // multiplies relu(W + b)
        PB = one_a * fmaxf(b, 0.0f) + upb + ud * a * b;
        NB = one_a * lower_d * b + ld * a * b;
    }
    g_P1[o] = P1; g_N1[o] = N1; g_P2[o] = P2;
    g_PB[o] = PB; g_NB[o] = NB;
    g_nrb[o]  = -fmaxf(b, 0.0f);
    g_bias[o] = b;
    if (P2 != 0.0f) atomicOr(&g_anyC2, 1);
}

// ---------------- kernel 2: C1/C2 matrices + ubias + D --------------------
__global__ void kern_coeff(const float* __restrict__ last_uA,
                           float* __restrict__ ubias_out) {
    int s = blockIdx.x;
    const float* row = last_uA + (size_t)s * O_DIM;
    float* c1row = g_C1 + (size_t)s * O_DIM;
    float* c2row = g_C2 + (size_t)s * O_DIM;

    float accB = 0.0f, accD = 0.0f;
    for (int o = threadIdx.x; o < O_DIM; o += blockDim.x) {
        float u = row[o];
        float p = fmaxf(u, 0.0f);
        float n = fminf(u, 0.0f);
        float c1 = p * g_P1[o] + n * g_N1[o];
        float c2 = p * g_P2[o];
        c1row[o] = c1;
        c2row[o] = c2;
        accB = fmaf(p, g_PB[o], accB);
        accB = fmaf(n, g_NB[o], accB);
        accD = fmaf(c2, g_nrb[o], accD);
    }
    // block reduction
    __shared__ float sB[8];
    __shared__ float sD[8];
    #pragma unroll
    for (int off = 16; off > 0; off >>= 1) {
        accB += __shfl_down_sync(0xffffffffu, accB, off);
        accD += __shfl_down_sync(0xffffffffu, accD, off);
    }
    int wid = threadIdx.x >> 5, lid = threadIdx.x & 31;
    if (lid == 0) { sB[wid] = accB; sD[wid] = accD; }
    __syncthreads();
    if (threadIdx.x == 0) {
        float tB = 0.0f, tD = 0.0f;
        #pragma unroll
        for (int w = 0; w < 8; w++) { tB += sB[w]; tD += sD[w]; }
        ubias_out[s] = tB;
        g_D[s] = tD;
    }
}

// ---------------- kernel 3: fused GEMM -------------------------------------
// uA[s,i] = sum_o C1[s,o]*W[o,i] + C2[s,o]*relu(W[o,i]+b[o]) + D[s]
#define BM 128
#define BN 128
#define BK 16
#define TM 8
#define TN 8
#define APAD 4

__global__ __launch_bounds__(256) void kern_gemm(const float* __restrict__ W,
                                                 float* __restrict__ out) {
    __shared__ float As [BK][BM + APAD];
    __shared__ float As2[BK][BM + APAD];
    __shared__ float Bs [BK][BN];
    __shared__ float bks[BK];

    const int bn  = blockIdx.x * BN;
    const int bm  = blockIdx.y * BM;
    const int tid = threadIdx.x;
    const int tx  = tid & 15;     // n direction (0..15)
    const int ty  = tid >> 4;     // m direction (0..15)

    const bool useC2 = (g_anyC2 != 0);

    float acc[TM][TN];
    #pragma unroll
    for (int i = 0; i < TM; i++)
        #pragma unroll
        for (int j = 0; j < TN; j++) acc[i][j] = 0.0f;

    // A tile loads: 128 rows x 16 k, float4 along k; each thread 2 rows
    const int a_m = tid >> 2;          // 0..63
    const int a_k = (tid & 3) * 4;     // 0,4,8,12
    // B tile loads: 16 k-rows x 128 n, float4 along n; each thread 2 rows
    const int b_k = tid >> 5;          // 0..7
    const int b_n = (tid & 31) * 4;

    const float* c1base = g_C1 + (size_t)(bm + a_m) * O_DIM + a_k;
    const float* c2base = g_C2 + (size_t)(bm + a_m) * O_DIM + a_k;

    for (int k0 = 0; k0 < O_DIM; k0 += BK) {
        // --- load A (C1) transposed ---
        float4 v0 = *(const float4*)(c1base + k0);
        float4 v1 = *(const float4*)(c1base + (size_t)64 * O_DIM + k0);
        As[a_k + 0][a_m]      = v0.x;
        As[a_k + 1][a_m]      = v0.y;
        As[a_k + 2][a_m]      = v0.z;
        As[a_k + 3][a_m]      = v0.w;
        As[a_k + 0][a_m + 64] = v1.x;
        As[a_k + 1][a_m + 64] = v1.y;
        As[a_k + 2][a_m + 64] = v1.z;
        As[a_k + 3][a_m + 64] = v1.w;
        if (useC2) {
            float4 u0 = *(const float4*)(c2base + k0);
            float4 u1 = *(const float4*)(c2base + (size_t)64 * O_DIM + k0);
            As2[a_k + 0][a_m]      = u0.x;
            As2[a_k + 1][a_m]      = u0.y;
            As2[a_k + 2][a_m]      = u0.z;
            As2[a_k + 3][a_m]      = u0.w;
            As2[a_k + 0][a_m + 64] = u1.x;
            As2[a_k + 1][a_m + 64] = u1.y;
            As2[a_k + 2][a_m + 64] = u1.z;
            As2[a_k + 3][a_m + 64] = u1.w;
            if (tid < BK) bks[tid] = g_bias[k0 + tid];
        }
        // --- load B (W) ---
        const float* wb = W + (size_t)(k0 + b_k) * I_DIM + bn + b_n;
        float4 w0 = *(const float4*)wb;
        float4 w1 = *(const float4*)(wb + (size_t)8 * I_DIM);
        *(float4*)&Bs[b_k][b_n]     = w0;
        *(float4*)&Bs[b_k + 8][b_n] = w1;
        __syncthreads();

        if (useC2) {
            #pragma unroll
            for (int k = 0; k < BK; k++) {
                float aF[TM], a2F[TM], bF[TN], rF[TN];
                float bkv = bks[k];
                #pragma unroll
                for (int i = 0; i < TM; i++) {
                    aF[i]  = As [k][ty * TM + i];
                    a2F[i] = As2[k][ty * TM + i];
                }
                #pragma unroll
                for (int j = 0; j < TN; j++) {
                    bF[j] = Bs[k][tx * TN + j];
                    rF[j] = fmaxf(bF[j] + bkv, 0.0f);
                }
                #pragma unroll
                for (int i = 0; i < TM; i++)
                    #pragma unroll
                    for (int j = 0; j < TN; j++)
                        acc[i][j] = fmaf(a2F[i], rF[j],
                                    fmaf(aF[i], bF[j], acc[i][j]));
            }
        } else {
            #pragma unroll
            for (int k = 0; k < BK; k++) {
                float4 a0 = *(const float4*)&As[k][ty * TM];
                float4 a1 = *(const float4*)&As[k][ty * TM + 4];
                float4 b0 = *(const float4*)&Bs[k][tx * TN];
                float4 b1 = *(const float4*)&Bs[k][tx * TN + 4];
                float aF[TM] = {a0.x, a0.y, a0.z, a0.w, a1.x, a1.y, a1.z, a1.w};
                float bF[TN] = {b0.x, b0.y, b0.z, b0.w, b1.x, b1.y, b1.z, b1.w};
                #pragma unroll
                for (int i = 0; i < TM; i++)
                    #pragma unroll
                    for (int j = 0; j < TN; j++)
                        acc[i][j] = fmaf(aF[i], bF[j], acc[i][j]);
            }
        }
        __syncthreads();
    }

    // epilogue: add per-row constant D[s], write out
    #pragma unroll
    for (int i = 0; i < TM; i++) {
        int m = bm + ty * TM + i;
        float d = g_D[m];
        float* orow = out + (size_t)m * I_DIM + bn + tx * TN;
        float4 r0, r1;
        r0.x = acc[i][0] + d; r0.y = acc[i][1] + d;
        r0.z = acc[i][2] + d; r0.w = acc[i][3] + d;
        r1.x = acc[i][4] + d; r1.y = acc[i][5] + d;
        r1.z = acc[i][6] + d; r1.w = acc[i][7] + d;
        *(float4*)(orow)     = r0;
        *(float4*)(orow + 4) = r1;
    }
}

// ---------------- launch ----------------------------------------------------
extern "C" void kernel_launch(void* const* d_in, const int* in_sizes, int n_in,
                              void* d_out, int out_size) {
    const float* last_uA = (const float*)d_in[0];  // [1, 512, 4096]
    const float* weight  = (const float*)d_in[1];  // [4096, 4096]
    const float* bias    = (const float*)d_in[2];  // [4096]
    const float* lbp     = (const float*)d_in[3];  // [1, 4096]
    const float* ubp     = (const float*)d_in[4];  // [1, 4096]
    const float* alpha   = (const float*)d_in[5];  // [1, 4096, 1]
    float* out = (float*)d_out;                    // uA then ubias

    kern_zero<<<1, 1>>>();
    kern_prep<<<O_DIM / 256, 256>>>(bias, lbp, ubp, alpha);
    kern_coeff<<<S_DIM, 256>>>(last_uA, out + (size_t)S_DIM * I_DIM);
    dim3 grid(I_DIM / BN, S_DIM / BM);
    kern_gemm<<<grid, 256>>>(weight, out);
}

// round 4
// speedup vs baseline: 2.6009x; 2.6009x over previous
#include <cuda_runtime.h>
#include <cuda_bf16.h>
#include <cstdint>

#define S_DIM 512
#define O_DIM 4096
#define I_DIM 4096

// ===================== device-global scratch ===============================
__device__ float g_P1[O_DIM], g_N1[O_DIM], g_P2[O_DIM], g_PB[O_DIM], g_NB[O_DIM];
__device__ float g_nrb[O_DIM];
__device__ float g_D[S_DIM];
__device__ int   g_anyC2;

__device__ __align__(16) __nv_bfloat16 g_Ahi [S_DIM * O_DIM];
__device__ __align__(16) __nv_bfloat16 g_Alo [S_DIM * O_DIM];
__device__ __align__(16) __nv_bfloat16 g_A2hi[S_DIM * O_DIM];
__device__ __align__(16) __nv_bfloat16 g_A2lo[S_DIM * O_DIM];
__device__ __align__(16) __nv_bfloat16 g_Whi [(size_t)O_DIM * I_DIM];
__device__ __align__(16) __nv_bfloat16 g_Wlo [(size_t)O_DIM * I_DIM];
__device__ __align__(16) __nv_bfloat16 g_Rhi [(size_t)O_DIM * I_DIM];
__device__ __align__(16) __nv_bfloat16 g_Rlo [(size_t)O_DIM * I_DIM];

__device__ __forceinline__ void split_bf16(float x, __nv_bfloat16& h, __nv_bfloat16& l) {
    h = __float2bfloat16(x);
    l = __float2bfloat16(x - __bfloat162float(h));
}

__device__ __forceinline__ uint32_t smem_u32(const void* p) {
    uint32_t a;
    asm("{ .reg .u64 t; cvta.to.shared.u64 t, %1; cvt.u32.u64 %0, t; }"
        : "=r"(a) : "l"(p));
    return a;
}
#define CP_ASYNC16(s, g) \
    asm volatile("cp.async.cg.shared.global [%0], [%1], 16;" :: "r"(s), "l"(g))
#define CP_COMMIT() asm volatile("cp.async.commit_group;" ::: "memory")
#define CP_WAIT1()  asm volatile("cp.async.wait_group 1;" ::: "memory")
#define CP_WAIT0()  asm volatile("cp.async.wait_group 0;" ::: "memory")

__device__ __forceinline__ void ldmx4(uint32_t* r, uint32_t addr) {
    asm volatile("ldmatrix.sync.aligned.m8n8.x4.shared.b16 {%0,%1,%2,%3}, [%4];"
                 : "=r"(r[0]), "=r"(r[1]), "=r"(r[2]), "=r"(r[3]) : "r"(addr));
}
__device__ __forceinline__ void ldmx2t(uint32_t* r, uint32_t addr) {
    asm volatile("ldmatrix.sync.aligned.m8n8.x2.trans.shared.b16 {%0,%1}, [%2];"
                 : "=r"(r[0]), "=r"(r[1]) : "r"(addr));
}
__device__ __forceinline__ void mma_bf16(float* c, const uint32_t* a, const uint32_t* b) {
    asm volatile("mma.sync.aligned.m16n8k16.row.col.f32.bf16.bf16.f32 "
                 "{%0,%1,%2,%3}, {%4,%5,%6,%7}, {%8,%9}, {%0,%1,%2,%3};"
                 : "+f"(c[0]), "+f"(c[1]), "+f"(c[2]), "+f"(c[3])
                 : "r"(a[0]), "r"(a[1]), "r"(a[2]), "r"(a[3]), "r"(b[0]), "r"(b[1]));
}

// ===================== kernel 0/1: flag + per-neuron scalars ===============
__global__ void kern_zero() { g_anyC2 = 0; }

__global__ void kern_prep(const float* __restrict__ bias,
                          const float* __restrict__ lbp,
                          const float* __restrict__ ubp,
                          const float* __restrict__ alpha) {
    int o = blockIdx.x * blockDim.x + threadIdx.x;
    if (o >= O_DIM) return;
    float b  = bias[o];
    float lb = lbp[o];
    float ub = ubp[o];
    float a  = alpha[o];
    float one_a = 1.0f - a;

    float lb_r = fminf(lb, 0.0f);
    float ub_r = fmaxf(ub, 0.0f);
    ub_r = fmaxf(ub_r, lb_r + 1e-8f);
    float ud  = ub_r / (ub_r - lb_r);
    float upb = -lb_r * ud;
    float ld  = (ud > 0.5f) ? 1.0f : 0.0f;
    float lower_d = (fabsf(lb) >= fabsf(ub)) ? 1.0f : 0.0f;

    float P1, N1, P2, PB, NB;
    if (ub <= 0.0f) {
        P1 = a * ud;            N1 = a * ld;                     P2 = 0.0f;
        PB = upb + ud * a * b;  NB = ld * a * b;
    } else if (lb >= 0.0f) {
        P1 = a * ud + one_a;    N1 = a * ld + one_a;             P2 = 0.0f;
        PB = one_a * b + upb + ud * a * b;
        NB = one_a * b + ld * a * b;
    } else {
        P1 = a * ud;            N1 = a * ld + one_a * lower_d;   P2 = one_a;
        PB = one_a * fmaxf(b, 0.0f) + upb + ud * a * b;
        NB = one_a * lower_d * b + ld * a * b;
    }
    g_P1[o] = P1; g_N1[o] = N1; g_P2[o] = P2;
    g_PB[o] = PB; g_NB[o] = NB;
    g_nrb[o] = -fmaxf(b, 0.0f);
    if (P2 != 0.0f) atomicOr(&g_anyC2, 1);
}

// ===================== kernel 2: coefficients (bf16-split) + ubias + D =====
__global__ void kern_coeff(const float* __restrict__ last_uA,
                           float* __restrict__ ubias_out) {
    int s = blockIdx.x;
    const bool useC2 = (g_anyC2 != 0);
    const float* row = last_uA + (size_t)s * O_DIM;

    float accB = 0.0f, accD = 0.0f;
    for (int o = threadIdx.x; o < O_DIM; o += blockDim.x) {
        float u = row[o];
        float p = fmaxf(u, 0.0f);
        float n = fminf(u, 0.0f);
        float c1 = p * g_P1[o] + n * g_N1[o];
        float c2 = p * g_P2[o];
        size_t idx = (size_t)s * O_DIM + o;
        __nv_bfloat16 h, l;
        split_bf16(c1, h, l);
        g_Ahi[idx] = h; g_Alo[idx] = l;
        if (useC2) {
            split_bf16(c2, h, l);
            g_A2hi[idx] = h; g_A2lo[idx] = l;
        }
        accB = fmaf(p, g_PB[o], accB);
        accB = fmaf(n, g_NB[o], accB);
        accD = fmaf(c2, g_nrb[o], accD);
    }
    __shared__ float sB[8], sD[8];
    #pragma unroll
    for (int off = 16; off > 0; off >>= 1) {
        accB += __shfl_down_sync(0xffffffffu, accB, off);
        accD += __shfl_down_sync(0xffffffffu, accD, off);
    }
    int wid = threadIdx.x >> 5, lid = threadIdx.x & 31;
    if (lid == 0) { sB[wid] = accB; sD[wid] = accD; }
    __syncthreads();
    if (threadIdx.x == 0) {
        float tB = 0.0f, tD = 0.0f;
        #pragma unroll
        for (int w = 0; w < 8; w++) { tB += sB[w]; tD += sD[w]; }
        ubias_out[s] = tB;
        g_D[s] = tD;
    }
}

// ===================== kernel 3: elementwise W split (no transpose!) =======
__global__ void kern_wsplit(const float* __restrict__ W,
                            const float* __restrict__ bias) {
    const bool useC2 = (g_anyC2 != 0);
    size_t base = ((size_t)blockIdx.x * blockDim.x + threadIdx.x) * 4;
    float4 w4 = *(const float4*)(W + base);
    float wv[4] = {w4.x, w4.y, w4.z, w4.w};
    __nv_bfloat16 h, l;
    #pragma unroll
    for (int j = 0; j < 4; j++) {
        split_bf16(wv[j], h, l);
        g_Whi[base + j] = h; g_Wlo[base + j] = l;
    }
    if (useC2) {
        int o = (int)(base >> 12);   // base / 4096
        float b = bias[o];
        #pragma unroll
        for (int j = 0; j < 4; j++) {
            split_bf16(fmaxf(wv[j] + b, 0.0f), h, l);
            g_Rhi[base + j] = h; g_Rlo[base + j] = l;
        }
    }
}

// ===================== kernel 4: mma.sync split-bf16 GEMM ===================
// out[m,i] = sum_o C1[m,o]*W[o,i] (+ C2[m,o]*relu(W[o,i]+b[o])) + D[m]
#define BM 128
#define BN 128
#define BK 32
#define LDA 40            // (BK+8) bf16 elems, 80 bytes/row
#define LDB 136           // (BN+8) bf16 elems, 272 bytes/row
#define A_BYTES (BM * LDA * 2)        // 10240
#define B_BYTES (BK * LDB * 2)        // 8704
#define STAGE   (2 * A_BYTES + 2 * B_BYTES)   // 37888
#define SMEM_DYN (2 * STAGE)

__global__ void __launch_bounds__(256, 1)
kern_gemm_mma(float* __restrict__ out) {
    extern __shared__ char sm[];
    const uint32_t sbase = smem_u32(sm);

    const int tid  = threadIdx.x;
    const int wid  = tid >> 5;
    const int lane = tid & 31;
    const int bn = blockIdx.x * BN;
    const int bm = blockIdx.y * BM;
    const bool useC2 = (g_anyC2 != 0);
    const int nK = useC2 ? 256 : 128;

    const int warp_m = wid & 1;      // 0..1  -> 64 rows each
    const int warp_n = wid >> 1;     // 0..3  -> 32 cols each

    float acc[4][4][4];
    #pragma unroll
    for (int mi = 0; mi < 4; mi++)
        #pragma unroll
        for (int ni = 0; ni < 4; ni++)
            #pragma unroll
            for (int q = 0; q < 4; q++) acc[mi][ni][q] = 0.0f;

    // ---- load geometry: 512 16B-chunks per matrix per stage, 2 per thread
    const int acRow0 = tid >> 2,        acCol0 = tid & 3;        // chunk tid
    const int acRow1 = (tid + 256) >> 2, acCol1 = tid & 3;       // chunk tid+256
    const int bcRow0 = tid >> 4,        bcCol0 = tid & 15;
    const int bcRow1 = (tid + 256) >> 4, bcCol1 = tid & 15;

    auto load_stage = [&](int ktL) {
        const int buf = ktL & 1;
        const int k0 = (ktL & 127) * BK;
        const __nv_bfloat16 *pAh, *pAl, *pBh, *pBl;
        if (ktL < 128) { pAh = g_Ahi;  pAl = g_Alo;  pBh = g_Whi; pBl = g_Wlo; }
        else           { pAh = g_A2hi; pAl = g_A2lo; pBh = g_Rhi; pBl = g_Rlo; }
        const uint32_t sAh = sbase + buf * STAGE;
        const uint32_t sAl = sAh + A_BYTES;
        const uint32_t sBh = sAl + A_BYTES;
        const uint32_t sBl = sBh + B_BYTES;

        size_t gA0 = (size_t)(bm + acRow0) * O_DIM + k0 + acCol0 * 8;
        size_t gA1 = (size_t)(bm + acRow1) * O_DIM + k0 + acCol1 * 8;
        uint32_t sA0 = acRow0 * (LDA * 2) + acCol0 * 16;
        uint32_t sA1 = acRow1 * (LDA * 2) + acCol1 * 16;
        CP_ASYNC16(sAh + sA0, pAh + gA0);
        CP_ASYNC16(sAh + sA1, pAh + gA1);
        CP_ASYNC16(sAl + sA0, pAl + gA0);
        CP_ASYNC16(sAl + sA1, pAl + gA1);

        size_t gB0 = (size_t)(k0 + bcRow0) * I_DIM + bn + bcCol0 * 8;
        size_t gB1 = (size_t)(k0 + bcRow1) * I_DIM + bn + bcCol1 * 8;
        uint32_t sB0 = bcRow0 * (LDB * 2) + bcCol0 * 16;
        uint32_t sB1 = bcRow1 * (LDB * 2) + bcCol1 * 16;
        CP_ASYNC16(sBh + sB0, pBh + gB0);
        CP_ASYNC16(sBh + sB1, pBh + gB1);
        CP_ASYNC16(sBl + sB0, pBl + gB0);
        CP_ASYNC16(sBl + sB1, pBl + gB1);
    };

    load_stage(0); CP_COMMIT();
    load_stage(1); CP_COMMIT();

    // per-thread ldmatrix offsets
    const uint32_t aoff = (warp_m * 64 + (lane & 15)) * (LDA * 2) + (lane >> 4) * 16;
    const uint32_t boff = (lane & 15) * (LDB * 2) + warp_n * 64;

    for (int kt = 0; kt < nK; kt++) {
        CP_WAIT1();
        __syncthreads();
        const int buf = kt & 1;
        const uint32_t sAh = sbase + buf * STAGE;
        const uint32_t sAl = sAh + A_BYTES;
        const uint32_t sBh = sAl + A_BYTES;
        const uint32_t sBl = sBh + B_BYTES;

        #pragma unroll
        for (int ks = 0; ks < 2; ks++) {
            uint32_t ah[4][4], al[4][4], bh[4][2], bl[4][2];
            #pragma unroll
            for (int mi = 0; mi < 4; mi++) {
                uint32_t a = aoff + mi * 16 * (LDA * 2) + ks * 32;
                ldmx4(ah[mi], sAh + a);
                ldmx4(al[mi], sAl + a);
            }
            #pragma unroll
            for (int ni = 0; ni < 4; ni++) {
                uint32_t b = boff + ks * 16 * (LDB * 2) + ni * 16;
                ldmx2t(bh[ni], sBh + b);
                ldmx2t(bl[ni], sBl + b);
            }
            #pragma unroll
            for (int mi = 0; mi < 4; mi++)
                #pragma unroll
                for (int ni = 0; ni < 4; ni++) {
                    mma_bf16(acc[mi][ni], ah[mi], bh[ni]);
                    mma_bf16(acc[mi][ni], ah[mi], bl[ni]);
                    mma_bf16(acc[mi][ni], al[mi], bh[ni]);
                }
        }
        __syncthreads();
        if (kt + 2 < nK) load_stage(kt + 2);
        CP_COMMIT();
    }

    // ---- epilogue: add D[m], write float2 per fragment pair
    #pragma unroll
    for (int mi = 0; mi < 4; mi++) {
        const int r0 = bm + warp_m * 64 + mi * 16 + (lane >> 2);
        const int r1 = r0 + 8;
        const float d0 = g_D[r0];
        const float d1 = g_D[r1];
        #pragma unroll
        for (int ni = 0; ni < 4; ni++) {
            const int c = bn + warp_n * 32 + ni * 8 + (lane & 3) * 2;
            float2 v0 = {acc[mi][ni][0] + d0, acc[mi][ni][1] + d0};
            float2 v1 = {acc[mi][ni][2] + d1, acc[mi][ni][3] + d1};
            *(float2*)(out + (size_t)r0 * I_DIM + c) = v0;
            *(float2*)(out + (size_t)r1 * I_DIM + c) = v1;
        }
    }
}

// ===================== launch ==============================================
extern "C" void kernel_launch(void* const* d_in, const int* in_sizes, int n_in,
                              void* d_out, int out_size) {
    const float* last_uA = (const float*)d_in[0];  // [1, 512, 4096]
    const float* weight  = (const float*)d_in[1];  // [4096, 4096]
    const float* bias    = (const float*)d_in[2];  // [4096]
    const float* lbp     = (const float*)d_in[3];  // [1, 4096]
    const float* ubp     = (const float*)d_in[4];  // [1, 4096]
    const float* alpha   = (const float*)d_in[5];  // [1, 4096, 1]
    float* out = (float*)d_out;                    // uA then ubias

    static int attr_done = 0;
    if (!attr_done) {
        cudaFuncSetAttribute(kern_gemm_mma,
                             cudaFuncAttributeMaxDynamicSharedMemorySize, SMEM_DYN);
        attr_done = 1;
    }

    kern_zero<<<1, 1>>>();
    kern_prep<<<O_DIM / 256, 256>>>(bias, lbp, ubp, alpha);
    kern_coeff<<<S_DIM, 256>>>(last_uA, out + (size_t)S_DIM * I_DIM);
    kern_wsplit<<<(int)(((size_t)O_DIM * I_DIM / 4) / 256), 256>>>(weight, bias);
    kern_gemm_mma<<<dim3(I_DIM / BN, S_DIM / BM), 256, SMEM_DYN>>>(out);
}